// round 16
// baseline (speedup 1.0000x reference)
#include <cuda_runtime.h>
#include <cuda_fp16.h>
#include <cstdint>

// Problem constants
#define PB   4
#define PK   2048
#define PD   1024
#define PH   16
#define PNC  1024   // NCTX = K/2

#define PANEL 8192      // fp16 elems per 128x64 tile panel (16KB)
#define APAN  4096      // fp16 elems per 64x64 attention panel (8KB)
#define ATT_T (PB * PH * 16 * APAN)

// ---------------- scratch (device globals: allocation-free) ----------------
__device__ __align__(256) int g_perm[PB * PK];
__device__ __align__(256) __half g_a2 [64ll * 32 * PANEL];
__device__ __align__(256) __half g_wc [24ll * 16 * PANEL];
__device__ __align__(256) __half g_wt [24ll * 16 * PANEL];
__device__ __align__(256) __half g_wco[ 8ll * 16 * PANEL];
__device__ __align__(256) __half g_wto[ 8ll * 16 * PANEL];
__device__ __align__(256) __half g_oc2[32ll * 16 * PANEL];   // attn out, hi only
__device__ __align__(256) __half g_ot2[32ll * 16 * PANEL];
// attention panels: 0..5 ctx {Qh,Ql,Kh,Kl,Vh,Vl(unused)}, 6..11 tgt
__device__ __align__(256) __half g_ap[12ll * ATT_T];

// ---------------- PTX helpers (base-PTX only) ----------------
__device__ __forceinline__ uint32_t smem_u32(const void* p) {
    uint32_t a;
    asm("{ .reg .u64 t; cvta.to.shared.u64 t, %1; cvt.u32.u64 %0, t; }" : "=r"(a) : "l"(p));
    return a;
}

__device__ __forceinline__ void cp_async16(uint32_t s, const void* g) {
    asm volatile("cp.async.cg.shared.global [%0], [%1], 16;" :: "r"(s), "l"(g));
}
#define CP_COMMIT() asm volatile("cp.async.commit_group;" ::: "memory")
#define CP_WAIT(n)  asm volatile("cp.async.wait_group %0;" :: "n"(n) : "memory")

__device__ __forceinline__ void ldmat_x4(uint32_t* r, uint32_t addr) {
    asm volatile("ldmatrix.sync.aligned.m8n8.x4.shared.b16 {%0,%1,%2,%3}, [%4];"
                 : "=r"(r[0]), "=r"(r[1]), "=r"(r[2]), "=r"(r[3]) : "r"(addr));
}

__device__ __forceinline__ void ldmat_x4_trans(uint32_t* r, uint32_t addr) {
    asm volatile("ldmatrix.sync.aligned.m8n8.x4.trans.shared.b16 {%0,%1,%2,%3}, [%4];"
                 : "=r"(r[0]), "=r"(r[1]), "=r"(r[2]), "=r"(r[3]) : "r"(addr));
}

__device__ __forceinline__ void mma16816(float* c, const uint32_t* a,
                                         uint32_t b0, uint32_t b1) {
    asm volatile(
        "mma.sync.aligned.m16n8k16.row.col.f32.f16.f16.f32 "
        "{%0,%1,%2,%3}, {%4,%5,%6,%7}, {%8,%9}, {%0,%1,%2,%3};"
        : "+f"(c[0]), "+f"(c[1]), "+f"(c[2]), "+f"(c[3])
        : "r"(a[0]), "r"(a[1]), "r"(a[2]), "r"(a[3]), "r"(b0), "r"(b1));
}

__device__ __forceinline__ uint32_t packh2(float lo, float hi) {
    __half2 h = __floats2half2_rn(lo, hi);
    return *(uint32_t*)&h;
}

__device__ __forceinline__ void split2h(float vx, float vy,
                                        uint32_t& uhi, uint32_t& ulo) {
    __half2 h = __floats2half2_rn(vx, vy);
    uhi = *(uint32_t*)&h;
    float hx = __half2float(__low2half(h));
    float hy = __half2float(__high2half(h));
    ulo = packh2(vx - hx, vy - hy);
}

__device__ __forceinline__ uint32_t sw128(uint32_t off) {
    return off ^ ((off >> 3) & 0x70);
}

// ---------------- perm (dtype-agnostic detection) ----------------
__global__ void build_perm(const void* __restrict__ is_ctx_raw) {
    const unsigned char* u8  = (const unsigned char*)is_ctx_raw;
    const unsigned int*  u32 = (const unsigned int*)is_ctx_raw;
    int b = blockIdx.x;
    int lane = threadIdx.x;

    int s = 0;
    for (int i = lane; i < 2048; i += 32) s += (int)u8[i];
#pragma unroll
    for (int off = 16; off; off >>= 1) s += __shfl_xor_sync(0xffffffffu, s, off);
    bool one_byte = (s == 1024) || (s == 255 * 1024);

    int cbase = 0, tbase = PNC;
    for (int j0 = 0; j0 < PK; j0 += 32) {
        int j = j0 + lane;
        int c = one_byte ? (u8[b * PK + j] != 0) : (u32[b * PK + j] != 0u);
        unsigned mask = __ballot_sync(0xffffffffu, c);
        int pre = __popc(mask & ((1u << lane) - 1u));
        int slot = c ? (cbase + pre) : (tbase + lane - pre);
        g_perm[b * PK + slot] = j;
        int nc = __popc(mask);
        cbase += nc;
        tbase += 32 - nc;
    }
}

// ---------------- RoPE + gather -> a2 panels directly -----------------------
__global__ __launch_bounds__(512) void rope_gather(
    const float* __restrict__ x, const float* __restrict__ coords,
    const float* __restrict__ rope) {
    int s = blockIdx.x & (PK - 1);
    int b = blockIdx.x >> 11;
    int j = g_perm[b * PK + s];
    long tokin = (long)b * PK + j;

    float cy = coords[tokin * 2 + 0];
    float cx = coords[tokin * 2 + 1];
    int ypos = (int)fminf(fmaxf(cy / 224.0f * 1023.0f, 0.0f), 1023.0f);
    int xpos = (int)fminf(fmaxf(cx / 224.0f * 1023.0f, 0.0f), 1023.0f);

    int t = threadIdx.x;
    int i = t & 255;
    int pos = (t < 256) ? xpos : ypos;
    int base = (t < 256) ? (2 * i) : (512 + 2 * i);

    float c  = rope[((long)pos * 256 + i) * 2 + 0];
    float sn = rope[((long)pos * 256 + i) * 2 + 1];
    float2 p = *(const float2*)(x + tokin * PD + base);
    float rx = p.x * c - p.y * sn;
    float ry = p.x * sn + p.y * c;

    uint32_t uhi, ulo;
    split2h(rx, ry, uhi, ulo);

    int mbp = b * 16 + (s >> 7);
    int rowp = s & 127;
    int ck = base >> 6;
    uint32_t sw = sw128((uint32_t)(rowp * 128 + (base & 63) * 2));
    long pb = (long)mbp * 32;
    *(uint32_t*)((char*)(g_a2 + (pb + ck) * PANEL) + sw)      = uhi;
    *(uint32_t*)((char*)(g_a2 + (pb + 16 + ck) * PANEL) + sw) = ulo;
}

// ---------------- merged fp16-hi conversion of ALL weights ------------------
__global__ __launch_bounds__(256) void convert_w_all(
    const float* __restrict__ s_ci, const float* __restrict__ s_ti,
    const float* __restrict__ s_co, const float* __restrict__ s_to) {
    int gm = blockIdx.x >> 4;
    int kb = blockIdx.x & 15;
    const float* src;
    __half* dst;
    int mb;
    if (gm < 24)      { src = s_ci; dst = g_wc;  mb = gm; }
    else if (gm < 48) { src = s_ti; dst = g_wt;  mb = gm - 24; }
    else if (gm < 56) { src = s_co; dst = g_wco; mb = gm - 48; }
    else              { src = s_to; dst = g_wto; mb = gm - 56; }
    int kc0 = kb * 64;
    long pan = (long)mb * 16 + kb;

    int t = threadIdx.x;
#pragma unroll
    for (int q = 0; q < 4; q++) {
        int ch = t + q * 256;
        int r = ch >> 3;
        int c0 = (ch & 7) * 8;
        const float* sp = src + ((long)mb * 128 + r) * 1024 + kc0 + c0;
        float4 f0 = *(const float4*)sp;
        float4 f1 = *(const float4*)(sp + 4);
        float vals[8] = {f0.x, f0.y, f0.z, f0.w, f1.x, f1.y, f1.z, f1.w};
        union { __half h[8]; uint4 u; } pk;
#pragma unroll
        for (int e = 0; e < 8; e++) pk.h[e] = __float2half_rn(vals[e]);
        uint32_t sw = sw128((uint32_t)(r * 128 + c0 * 2));
        *(uint4*)((char*)(dst + pan * PANEL) + sw) = pk.u;
    }
}

// ---------------- GEMM mainloop, 2-term A (proj): ks staggered per warp -----
__device__ __forceinline__ void gemm_mainloop2(
    const char* pA, const char* pW, uint32_t tiles,
    int tid, int wid, int rA0, int rB0, int cb, uint32_t xm,
    float acc[2][8][4]) {
    {
        uint32_t sa = tiles;
#pragma unroll
        for (int q = 0; q < 12; q++) {
            int ch = tid + q * 256;
            int reg = ch >> 10;
            int idx = ch & 1023;
            const char* src = (reg == 0) ? (pA + idx * 16)
                            : (reg == 1) ? (pA + 16 * 16384 + idx * 16)
                                         : (pW + idx * 16);
            cp_async16(sa + ch * 16, src);
        }
        CP_COMMIT();
    }

    for (int kb = 0; kb < 16; kb++) {
        CP_WAIT(0);
        __syncthreads();
        if (kb + 1 < 16) {
            uint32_t sa = tiles + (uint32_t)((kb + 1) & 1) * 49152u;
            const char* gAh = pA + (long)(kb + 1) * 16384;
            const char* gAl = pA + (long)(16 + kb + 1) * 16384;
            const char* gW  = pW + (long)(kb + 1) * 16384;
#pragma unroll
            for (int q = 0; q < 12; q++) {
                int ch = tid + q * 256;
                int reg = ch >> 10;
                int idx = ch & 1023;
                const char* src = (reg == 0) ? (gAh + idx * 16)
                                : (reg == 1) ? (gAl + idx * 16)
                                             : (gW + idx * 16);
                cp_async16(sa + ch * 16, src);
            }
            CP_COMMIT();
        }

        uint32_t sA = tiles + (uint32_t)(kb & 1) * 49152u;
        uint32_t sW = sA + 32768u;
#pragma unroll
        for (int k0 = 0; k0 < 4; k0++) {
            int ks = (k0 + wid) & 3;
            uint32_t colb = (uint32_t)(cb + ks * 32) ^ xm;
            uint32_t bf[4][4];
#pragma unroll
            for (int np = 0; np < 4; np++)
                ldmat_x4(bf[np], sW + (uint32_t)(rB0 + np * 16) * 128u + colb);
#pragma unroll
            for (int half = 0; half < 2; half++) {
                uint32_t aB = sA + (uint32_t)half * 16384u;
                uint32_t af[2][4];
#pragma unroll
                for (int mt = 0; mt < 2; mt++)
                    ldmat_x4(af[mt], aB + (uint32_t)(rA0 + mt * 16) * 128u + colb);
#pragma unroll
                for (int mt = 0; mt < 2; mt++) {
#pragma unroll
                    for (int nt = 0; nt < 8; nt++) {
                        int np = nt >> 1;
                        int sel = nt & 1;
                        mma16816(acc[mt][nt], af[mt], bf[np][sel], bf[np][sel + 2]);
                    }
                }
            }
        }
    }
}

// ---------------- merged projection GEMM -> attention panels ----------------
// grid (48, 32): x<24 ctx qkv, x<40 tgt kv, else tgt q.
__global__ __launch_bounds__(256, 2) void gemm_proj(
    const float* __restrict__ ctx_in_b, const float* __restrict__ tgt_in_b) {
    extern __shared__ char dsm[];
    uint32_t base = smem_u32(dsm);
    uint32_t tiles = (base + 1023u) & ~1023u;

    int tid = threadIdx.x;
    int wid = tid >> 5;
    int lid = tid & 31;
    int wm = wid & 3;
    int wn = wid >> 2;

    int nx = blockIdx.x;
    const __half* Apan;
    const __half* Wpan;
    const float* bias;
    __half* apDst;
    float qscale;
    int nloc;
    if (nx < 24) {
        Apan = g_a2; Wpan = g_wc; bias = ctx_in_b;
        apDst = g_ap; qscale = 0.125f; nloc = nx;
    } else if (nx < 40) {
        Apan = g_a2; Wpan = g_wt + 8ll * 16 * PANEL; bias = tgt_in_b + 1024;
        apDst = g_ap + 8ll * ATT_T; qscale = 1.0f; nloc = nx - 24;
    } else {
        Apan = g_a2 + 8ll * 32 * PANEL; Wpan = g_wt; bias = tgt_in_b;
        apDst = g_ap + 6ll * ATT_T; qscale = 0.125f; nloc = nx - 40;
    }

    int by = blockIdx.y;
    int b = by >> 3;
    int l = by & 7;
    const char* pA = (const char*)(Apan + ((long)(b * 16 + l) * 32) * PANEL);
    const char* pW = (const char*)(Wpan + ((long)nloc * 16) * PANEL);

    float acc[2][8][4];
#pragma unroll
    for (int mt = 0; mt < 2; mt++)
#pragma unroll
        for (int nt = 0; nt < 8; nt++)
#pragma unroll
            for (int e = 0; e < 4; e++) acc[mt][nt][e] = 0.0f;

    int rA0 = wm * 32 + (lid & 15);
    int rB0 = wn * 64 + (lid & 15);
    int cb  = (lid >> 4) * 16;
    uint32_t xm = (uint32_t)((lid & 7) << 4);

    gemm_mainloop2(pA, pW, tiles, tid, wid, rA0, rB0, cb, xm, acc);

    int n0 = nloc * 128;
#pragma unroll
    for (int nt = 0; nt < 8; nt++) {
        int cc = wn * 64 + nt * 8 + (lid & 3) * 2;
        int ng = n0 + cc;
        int g = ng >> 10;
        int head = (ng >> 6) & 15;
        float sc = (g == 0) ? qscale : 1.0f;
        float bx = bias[ng];
        float by2 = bias[ng + 1];
        __half* hiB = apDst + (long)(2 * g) * ATT_T;
        __half* loB = apDst + (long)(2 * g + 1) * ATT_T;
        bool writeLo = (g != 2);   // V-lo panels are unused (PV 1-term)
#pragma unroll
        for (int mt = 0; mt < 2; mt++) {
            int r0 = wm * 32 + mt * 16 + (lid >> 2);
#pragma unroll
            for (int half = 0; half < 2; half++) {
                int tr = l * 128 + r0 + half * 8;
                int kt = tr >> 6;
                int row = tr & 63;
                float vx = (acc[mt][nt][half * 2 + 0] + bx) * sc;
                float vy = (acc[mt][nt][half * 2 + 1] + by2) * sc;
                uint32_t uhi, ulo;
                split2h(vx, vy, uhi, ulo);
                long pan = (((long)b * PH + head) * 16 + kt) * APAN;
                uint32_t sw = sw128((uint32_t)(row * 128 + (nt * 8 + (lid & 3) * 2) * 2));
                *(uint32_t*)((char*)(hiB + pan) + sw) = uhi;
                if (writeLo)
                    *(uint32_t*)((char*)(loB + pan) + sw) = ulo;
            }
        }
    }
}

// ---------------- output projection: 64x128 tiles, 3 CTAs/SM ----------------
// grid (8, 128): y<64 ctx (b=y>>4, sub=y&15), else tgt.
// 8 warps: wm = wid&1 (32 rows), wn = wid>>1 (32 cols). Stage [A 8K|W 16K].
__global__ __launch_bounds__(256, 3) void gemm_out(
    const float* __restrict__ ctx_out_b, const float* __restrict__ tgt_out_b,
    float* __restrict__ C) {
    extern __shared__ char dsm[];
    uint32_t base = smem_u32(dsm);
    uint32_t tiles = (base + 1023u) & ~1023u;

    int tid = threadIdx.x;
    int wid = tid >> 5;
    int lid = tid & 31;
    int wm = wid & 1;
    int wn = wid >> 1;

    int y = blockIdx.y;
    const __half* Apan;
    const __half* Wpan;
    const float* bias;
    int slotOff;
    if (y < 64) {
        Apan = g_oc2; Wpan = g_wco; bias = ctx_out_b; slotOff = 0;
    } else {
        Apan = g_ot2; Wpan = g_wto; bias = tgt_out_b; slotOff = PNC;
        y -= 64;
    }
    int b = y >> 4;
    int sub = y & 15;
    const char* pA = (const char*)(Apan + ((long)(b * 8 + (sub >> 1)) * 16) * PANEL)
                   + (sub & 1) * 8192;
    const char* pW = (const char*)(Wpan + ((long)blockIdx.x * 16) * PANEL);

    float acc[2][4][4];
#pragma unroll
    for (int mt = 0; mt < 2; mt++)
#pragma unroll
        for (int nt = 0; nt < 4; nt++)
#pragma unroll
            for (int e = 0; e < 4; e++) acc[mt][nt][e] = 0.0f;

    int rA0 = wm * 32 + (lid & 15) - wm * 16;   // wm0: rows 0..15(+mt16), wm1: 16..31? no:
    rA0 = wm * 32 + (lid & 15);                  // rows 0..47; +mt*16 -> 0..63? wm=1: 32+15+16=63 ok
    int rB0 = wn * 32 + (lid & 15);
    int cb  = (lid >> 4) * 16;
    uint32_t xm = (uint32_t)((lid & 7) << 4);

    // prologue
    {
        uint32_t sa = tiles;
#pragma unroll
        for (int q = 0; q < 6; q++) {
            int ch = tid + q * 256;
            const char* src = (ch < 512) ? (pA + ch * 16) : (pW + (ch - 512) * 16);
            cp_async16(sa + ch * 16, src);
        }
        CP_COMMIT();
    }

    for (int kb = 0; kb < 16; kb++) {
        CP_WAIT(0);
        __syncthreads();
        if (kb + 1 < 16) {
            uint32_t sa = tiles + (uint32_t)((kb + 1) & 1) * 24576u;
            const char* gA = pA + (long)(kb + 1) * 16384;
            const char* gW = pW + (long)(kb + 1) * 16384;
#pragma unroll
            for (int q = 0; q < 6; q++) {
                int ch = tid + q * 256;
                const char* src = (ch < 512) ? (gA + ch * 16) : (gW + (ch - 512) * 16);
                cp_async16(sa + ch * 16, src);
            }
            CP_COMMIT();
        }

        uint32_t sA = tiles + (uint32_t)(kb & 1) * 24576u;
        uint32_t sW = sA + 8192u;
#pragma unroll
        for (int k0 = 0; k0 < 4; k0++) {
            int ks = (k0 + wid) & 3;
            uint32_t colb = (uint32_t)(cb + ks * 32) ^ xm;
            uint32_t bf[2][4];
#pragma unroll
            for (int np = 0; np < 2; np++)
                ldmat_x4(bf[np], sW + (uint32_t)(rB0 + np * 16) * 128u + colb);
            uint32_t af[2][4];
#pragma unroll
            for (int mt = 0; mt < 2; mt++)
                ldmat_x4(af[mt], sA + (uint32_t)(rA0 + mt * 16) * 128u + colb);
#pragma unroll
            for (int mt = 0; mt < 2; mt++) {
#pragma unroll
                for (int nt = 0; nt < 4; nt++) {
                    int np = nt >> 1;
                    int sel = nt & 1;
                    mma16816(acc[mt][nt], af[mt], bf[np][sel], bf[np][sel + 2]);
                }
            }
        }
    }

    int n0 = blockIdx.x * 128;
#pragma unroll
    for (int nt = 0; nt < 4; nt++) {
        int cc = wn * 32 + nt * 8 + (lid & 3) * 2;
        float2 bv;
        bv.x = bias[n0 + cc];
        bv.y = bias[n0 + cc + 1];
#pragma unroll
        for (int mt = 0; mt < 2; mt++) {
            int r0 = wm * 32 + mt * 16 + (lid >> 2);
            float2 v0, v1;
            v0.x = acc[mt][nt][0] + bv.x;
            v0.y = acc[mt][nt][1] + bv.y;
            v1.x = acc[mt][nt][2] + bv.x;
            v1.y = acc[mt][nt][3] + bv.y;
            int tok0 = g_perm[b * PK + sub * 64 + r0 + slotOff];
            int tok1 = g_perm[b * PK + sub * 64 + r0 + 8 + slotOff];
            *(float2*)(C + ((long)b * PK + tok0) * PD + n0 + cc) = v0;
            *(float2*)(C + ((long)b * PK + tok1) * PD + n0 + cc) = v1;
        }
    }
}

// ---------------- merged fp16 HMMA flash attention --------------------------
// grid (8, 16, 8): z<4 ctx (b=z), else tgt (b=z-4). QK 3-term, PV 1-term.
__global__ __launch_bounds__(256, 2) void attn_mma() {
    extern __shared__ char dsm[];
    uint32_t base = smem_u32(dsm);
    uint32_t sQ = (base + 1023u) & ~1023u;     // Qh 16KB | Ql 16KB
    uint32_t sT = sQ + 32768u;                 // 2 stages x [Kh|Kl|Vh] 8KB each

    int tid = threadIdx.x, wid = tid >> 5, lid = tid & 31;
    int qt = blockIdx.x, h = blockIdx.y, z = blockIdx.z;
    int b;
    const __half* baseAp;
    __half* Opan;
    if (z < 4) { b = z;     baseAp = g_ap;                 Opan = g_oc2; }
    else       { b = z - 4; baseAp = g_ap + 6ll * ATT_T;   Opan = g_ot2; }

    long pb = ((long)b * PH + h) * 16;
    const char* pQh = (const char*)(baseAp + 0ll * ATT_T + (pb + qt * 2) * APAN);
    const char* pQl = (const char*)(baseAp + 1ll * ATT_T + (pb + qt * 2) * APAN);
    const char* pKh = (const char*)(baseAp + 2ll * ATT_T + pb * APAN);
    const char* pKl = (const char*)(baseAp + 3ll * ATT_T + pb * APAN);
    const char* pVh = (const char*)(baseAp + 4ll * ATT_T + pb * APAN);

#pragma unroll
    for (int q = 0; q < 8; q++) {
        int ch = tid + q * 256;
        int idx = ch & 1023;
        if (q < 4) cp_async16(sQ + idx * 16, pQh + idx * 16);
        else       cp_async16(sQ + 16384 + idx * 16, pQl + idx * 16);
    }
#pragma unroll
    for (int q = 0; q < 6; q++) {
        int ch = tid + q * 256;
        int idx = ch & 511;
        const char* s = (q < 2) ? pKh : (q < 4) ? pKl : pVh;
        cp_async16(sT + ch * 16, s + idx * 16);
    }
    CP_COMMIT();
    CP_WAIT(0);
    __syncthreads();

    int cb = (lid >> 4) * 16;
    uint32_t xm = (uint32_t)((lid & 7) << 4);

    uint32_t qra = sQ + (uint32_t)(wid >> 2) * 8192u
                 + (uint32_t)(((wid & 3) * 16 + (lid & 15)) * 128);
    uint32_t qhf[4][4], qlf[4][4];
#pragma unroll
    for (int ks = 0; ks < 4; ks++) {
        uint32_t col = (uint32_t)(ks * 32 + cb) ^ xm;
        ldmat_x4(qhf[ks], qra + col);
        ldmat_x4(qlf[ks], qra + 16384u + col);
    }

    float m0 = -1e30f, m1 = -1e30f, l0 = 0.0f, l1 = 0.0f;
    float oa[8][4];
#pragma unroll
    for (int nt = 0; nt < 8; nt++)
#pragma unroll
        for (int e = 0; e < 4; e++) oa[nt][e] = 0.0f;

    for (int kt = 0; kt < 16; kt++) {
        uint32_t st = sT + (uint32_t)(kt & 1) * 24576u;
        if (kt + 1 < 16) {
            uint32_t sn = sT + (uint32_t)((kt + 1) & 1) * 24576u;
            long off = (long)(kt + 1) * 8192;
#pragma unroll
            for (int q = 0; q < 6; q++) {
                int ch = tid + q * 256;
                int idx = ch & 511;
                const char* s = (q < 2) ? pKh : (q < 4) ? pKl : pVh;
                cp_async16(sn + ch * 16, s + off + idx * 16);
            }
            CP_COMMIT();
        }

        float sc[8][4];
#pragma unroll
        for (int nt = 0; nt < 8; nt++)
#pragma unroll
            for (int e = 0; e < 4; e++) sc[nt][e] = 0.0f;

#pragma unroll
        for (int k0 = 0; k0 < 4; k0++) {
            int ks = (k0 + wid) & 3;
            uint32_t col = (uint32_t)(ks * 32 + cb) ^ xm;
            uint32_t bh_[4][4], bl_[4][4];
#pragma unroll
            for (int np = 0; np < 4; np++) {
                uint32_t ra = (uint32_t)((np * 16 + (lid & 15)) * 128);
                ldmat_x4(bh_[np], st + ra + col);
                ldmat_x4(bl_[np], st + 8192u + ra + col);
            }
#pragma unroll
            for (int nt = 0; nt < 8; nt++) {
                int np = nt >> 1, sel = nt & 1;
                mma16816(sc[nt], qhf[ks], bh_[np][sel], bh_[np][sel + 2]);
                mma16816(sc[nt], qlf[ks], bh_[np][sel], bh_[np][sel + 2]);
                mma16816(sc[nt], qhf[ks], bl_[np][sel], bl_[np][sel + 2]);
            }
        }

        float mt0 = -1e30f, mt1 = -1e30f;
#pragma unroll
        for (int nt = 0; nt < 8; nt++) {
            mt0 = fmaxf(mt0, fmaxf(sc[nt][0], sc[nt][1]));
            mt1 = fmaxf(mt1, fmaxf(sc[nt][2], sc[nt][3]));
        }
        mt0 = fmaxf(mt0, __shfl_xor_sync(0xffffffffu, mt0, 1));
        mt0 = fmaxf(mt0, __shfl_xor_sync(0xffffffffu, mt0, 2));
        mt1 = fmaxf(mt1, __shfl_xor_sync(0xffffffffu, mt1, 1));
        mt1 = fmaxf(mt1, __shfl_xor_sync(0xffffffffu, mt1, 2));

        float mn0 = fmaxf(m0, mt0), mn1 = fmaxf(m1, mt1);
        float a0 = __expf(m0 - mn0), a1 = __expf(m1 - mn1);

        uint32_t php[8][2];
        float ps0 = 0.0f, ps1 = 0.0f;
#pragma unroll
        for (int nt = 0; nt < 8; nt++) {
            float p00 = __expf(sc[nt][0] - mn0);
            float p01 = __expf(sc[nt][1] - mn0);
            float p10 = __expf(sc[nt][2] - mn1);
            float p11 = __expf(sc[nt][3] - mn1);
            ps0 += p00 + p01;
            ps1 += p10 + p11;
            php[nt][0] = packh2(p00, p01);
            php[nt][1] = packh2(p10, p11);
        }
        ps0 += __shfl_xor_sync(0xffffffffu, ps0, 1);
        ps0 += __shfl_xor_sync(0xffffffffu, ps0, 2);
        ps1 += __shfl_xor_sync(0xffffffffu, ps1, 1);
        ps1 += __shfl_xor_sync(0xffffffffu, ps1, 2);

        l0 = l0 * a0 + ps0;
        l1 = l1 * a1 + ps1;
        m0 = mn0;
        m1 = mn1;
#pragma unroll
        for (int nt = 0; nt < 8; nt++) {
            oa[nt][0] *= a0; oa[nt][1] *= a0;
            oa[nt][2] *= a1; oa[nt][3] *= a1;
        }

#pragma unroll
        for (int k0 = 0; k0 < 4; k0++) {
            int ks = (k0 + wid) & 3;
            uint32_t ah[4] = {php[2 * ks][0], php[2 * ks][1],
                              php[2 * ks + 1][0], php[2 * ks + 1][1]};
            uint32_t vh_[4][4];
            uint32_t ra = (uint32_t)((ks * 16 + (lid & 15)) * 128);
#pragma unroll
            for (int np = 0; np < 4; np++) {
                uint32_t col = (uint32_t)(np * 32 + cb) ^ xm;
                ldmat_x4_trans(vh_[np], st + 16384u + ra + col);
            }
#pragma unroll
            for (int nt = 0; nt < 8; nt++) {
                int np = nt >> 1, s2 = (nt & 1) * 2;
                mma16816(oa[nt], ah, vh_[np][s2], vh_[np][s2 + 1]);
            }
        }

        if (kt + 1 < 16) CP_WAIT(0);
        __syncthreads();
    }

    // epilogue: hi-only A-panels [mb = b*8+qt][16 chunks]; chunk h
    float i0 = 1.0f / l0, i1 = 1.0f / l1;
    int rl = wid * 16 + (lid >> 2);
    long panB = ((long)b * 8 + qt) * 16;
    __half* c_hi = Opan + (panB + h) * (long)PANEL;
#pragma unroll
    for (int nt = 0; nt < 8; nt++) {
        int col = nt * 8 + (lid & 3) * 2;
        uint32_t sw0 = sw128((uint32_t)(rl * 128 + col * 2));
        uint32_t sw1 = sw128((uint32_t)((rl + 8) * 128 + col * 2));
        *(uint32_t*)((char*)c_hi + sw0) = packh2(oa[nt][0] * i0, oa[nt][1] * i0);
        *(uint32_t*)((char*)c_hi + sw1) = packh2(oa[nt][2] * i1, oa[nt][3] * i1);
    }
}

// ---------------- launch ----------------
extern "C" void kernel_launch(void* const* d_in, const int* in_sizes, int n_in,
                              void* d_out, int out_size) {
    const float* x         = (const float*)d_in[0];
    const float* coords    = (const float*)d_in[1];
    const void*  is_ctx    = d_in[2];
    const float* rope      = (const float*)d_in[3];
    const float* ctx_in_w  = (const float*)d_in[4];
    const float* ctx_in_b  = (const float*)d_in[5];
    const float* ctx_out_w = (const float*)d_in[6];
    const float* ctx_out_b = (const float*)d_in[7];
    const float* tgt_in_w  = (const float*)d_in[8];
    const float* tgt_in_b  = (const float*)d_in[9];
    const float* tgt_out_w = (const float*)d_in[10];
    const float* tgt_out_b = (const float*)d_in[11];
    float* out = (float*)d_out;

    const int GSM  = 1024 + 2 * 49152;           // 99328 (proj)
    const int GSM1 = 1024 + 2 * 24576;           // 50176 (out, 64x128)
    const int ASM  = 1024 + 32768 + 2 * 24576;   // 82944
    cudaFuncSetAttribute(gemm_proj, cudaFuncAttributeMaxDynamicSharedMemorySize, GSM);
    cudaFuncSetAttribute(gemm_out,  cudaFuncAttributeMaxDynamicSharedMemorySize, GSM1);
    cudaFuncSetAttribute(attn_mma,  cudaFuncAttributeMaxDynamicSharedMemorySize, ASM);

    build_perm<<<PB, 32>>>(is_ctx);
    rope_gather<<<PB * PK, 512>>>(x, coords, rope);
    convert_w_all<<<64 * 16, 256>>>(ctx_in_w, tgt_in_w, ctx_out_w, tgt_out_w);
    gemm_proj<<<dim3(48, 32), 256, GSM>>>(ctx_in_b, tgt_in_b);
    attn_mma<<<dim3(8, PH, 2 * PB), 256, ASM>>>();
    gemm_out<<<dim3(8, 128), 256, GSM1>>>(ctx_out_b, tgt_out_b, out);
}

// round 17
// speedup vs baseline: 1.0407x; 1.0407x over previous
#include <cuda_runtime.h>
#include <cuda_fp16.h>
#include <cstdint>

// Problem constants
#define PB   4
#define PK   2048
#define PD   1024
#define PH   16
#define PNC  1024   // NCTX = K/2

#define PANEL 8192      // fp16 elems per 128x64 tile panel (16KB)
#define APAN  4096      // fp16 elems per 64x64 attention panel (8KB)
#define ATT_T (PB * PH * 16 * APAN)

// ---------------- scratch (device globals: allocation-free) ----------------
__device__ __align__(256) int g_perm[PB * PK];
__device__ __align__(256) __half g_a2 [64ll * 32 * PANEL];
__device__ __align__(256) __half g_wc [24ll * 16 * PANEL];
__device__ __align__(256) __half g_wt [24ll * 16 * PANEL];
__device__ __align__(256) __half g_wco[ 8ll * 16 * PANEL];
__device__ __align__(256) __half g_wto[ 8ll * 16 * PANEL];
__device__ __align__(256) __half g_oc2[32ll * 16 * PANEL];   // attn out, hi only
__device__ __align__(256) __half g_ot2[32ll * 16 * PANEL];
// attention panels: 0..5 ctx {Qh,Ql,Kh,Kl,Vh,Vl(unused)}, 6..11 tgt
__device__ __align__(256) __half g_ap[12ll * ATT_T];

// ---------------- PTX helpers (base-PTX only) ----------------
__device__ __forceinline__ uint32_t smem_u32(const void* p) {
    uint32_t a;
    asm("{ .reg .u64 t; cvta.to.shared.u64 t, %1; cvt.u32.u64 %0, t; }" : "=r"(a) : "l"(p));
    return a;
}

__device__ __forceinline__ void cp_async16(uint32_t s, const void* g) {
    asm volatile("cp.async.cg.shared.global [%0], [%1], 16;" :: "r"(s), "l"(g));
}
#define CP_COMMIT() asm volatile("cp.async.commit_group;" ::: "memory")
#define CP_WAIT(n)  asm volatile("cp.async.wait_group %0;" :: "n"(n) : "memory")

__device__ __forceinline__ void ldmat_x4(uint32_t* r, uint32_t addr) {
    asm volatile("ldmatrix.sync.aligned.m8n8.x4.shared.b16 {%0,%1,%2,%3}, [%4];"
                 : "=r"(r[0]), "=r"(r[1]), "=r"(r[2]), "=r"(r[3]) : "r"(addr));
}

__device__ __forceinline__ void ldmat_x4_trans(uint32_t* r, uint32_t addr) {
    asm volatile("ldmatrix.sync.aligned.m8n8.x4.trans.shared.b16 {%0,%1,%2,%3}, [%4];"
                 : "=r"(r[0]), "=r"(r[1]), "=r"(r[2]), "=r"(r[3]) : "r"(addr));
}

__device__ __forceinline__ void mma16816(float* c, const uint32_t* a,
                                         uint32_t b0, uint32_t b1) {
    asm volatile(
        "mma.sync.aligned.m16n8k16.row.col.f32.f16.f16.f32 "
        "{%0,%1,%2,%3}, {%4,%5,%6,%7}, {%8,%9}, {%0,%1,%2,%3};"
        : "+f"(c[0]), "+f"(c[1]), "+f"(c[2]), "+f"(c[3])
        : "r"(a[0]), "r"(a[1]), "r"(a[2]), "r"(a[3]), "r"(b0), "r"(b1));
}

__device__ __forceinline__ uint32_t packh2(float lo, float hi) {
    __half2 h = __floats2half2_rn(lo, hi);
    return *(uint32_t*)&h;
}

__device__ __forceinline__ void split2h(float vx, float vy,
                                        uint32_t& uhi, uint32_t& ulo) {
    __half2 h = __floats2half2_rn(vx, vy);
    uhi = *(uint32_t*)&h;
    float hx = __half2float(__low2half(h));
    float hy = __half2float(__high2half(h));
    ulo = packh2(vx - hx, vy - hy);
}

__device__ __forceinline__ uint32_t sw128(uint32_t off) {
    return off ^ ((off >> 3) & 0x70);
}

// ---------------- perm (dtype-agnostic detection) ----------------
__global__ void build_perm(const void* __restrict__ is_ctx_raw) {
    const unsigned char* u8  = (const unsigned char*)is_ctx_raw;
    const unsigned int*  u32 = (const unsigned int*)is_ctx_raw;
    int b = blockIdx.x;
    int lane = threadIdx.x;

    int s = 0;
    for (int i = lane; i < 2048; i += 32) s += (int)u8[i];
#pragma unroll
    for (int off = 16; off; off >>= 1) s += __shfl_xor_sync(0xffffffffu, s, off);
    bool one_byte = (s == 1024) || (s == 255 * 1024);

    int cbase = 0, tbase = PNC;
    for (int j0 = 0; j0 < PK; j0 += 32) {
        int j = j0 + lane;
        int c = one_byte ? (u8[b * PK + j] != 0) : (u32[b * PK + j] != 0u);
        unsigned mask = __ballot_sync(0xffffffffu, c);
        int pre = __popc(mask & ((1u << lane) - 1u));
        int slot = c ? (cbase + pre) : (tbase + lane - pre);
        g_perm[b * PK + slot] = j;
        int nc = __popc(mask);
        cbase += nc;
        tbase += 32 - nc;
    }
}

// ---------------- RoPE + gather -> a2 panels directly -----------------------
__global__ __launch_bounds__(512) void rope_gather(
    const float* __restrict__ x, const float* __restrict__ coords,
    const float* __restrict__ rope) {
    int s = blockIdx.x & (PK - 1);
    int b = blockIdx.x >> 11;
    int j = g_perm[b * PK + s];
    long tokin = (long)b * PK + j;

    float cy = coords[tokin * 2 + 0];
    float cx = coords[tokin * 2 + 1];
    int ypos = (int)fminf(fmaxf(cy / 224.0f * 1023.0f, 0.0f), 1023.0f);
    int xpos = (int)fminf(fmaxf(cx / 224.0f * 1023.0f, 0.0f), 1023.0f);

    int t = threadIdx.x;
    int i = t & 255;
    int pos = (t < 256) ? xpos : ypos;
    int base = (t < 256) ? (2 * i) : (512 + 2 * i);

    float c  = rope[((long)pos * 256 + i) * 2 + 0];
    float sn = rope[((long)pos * 256 + i) * 2 + 1];
    float2 p = *(const float2*)(x + tokin * PD + base);
    float rx = p.x * c - p.y * sn;
    float ry = p.x * sn + p.y * c;

    uint32_t uhi, ulo;
    split2h(rx, ry, uhi, ulo);

    int mbp = b * 16 + (s >> 7);
    int rowp = s & 127;
    int ck = base >> 6;
    uint32_t sw = sw128((uint32_t)(rowp * 128 + (base & 63) * 2));
    long pb = (long)mbp * 32;
    *(uint32_t*)((char*)(g_a2 + (pb + ck) * PANEL) + sw)      = uhi;
    *(uint32_t*)((char*)(g_a2 + (pb + 16 + ck) * PANEL) + sw) = ulo;
}

// ---------------- merged fp16-hi conversion of ALL weights ------------------
__global__ __launch_bounds__(256) void convert_w_all(
    const float* __restrict__ s_ci, const float* __restrict__ s_ti,
    const float* __restrict__ s_co, const float* __restrict__ s_to) {
    int gm = blockIdx.x >> 4;
    int kb = blockIdx.x & 15;
    const float* src;
    __half* dst;
    int mb;
    if (gm < 24)      { src = s_ci; dst = g_wc;  mb = gm; }
    else if (gm < 48) { src = s_ti; dst = g_wt;  mb = gm - 24; }
    else if (gm < 56) { src = s_co; dst = g_wco; mb = gm - 48; }
    else              { src = s_to; dst = g_wto; mb = gm - 56; }
    int kc0 = kb * 64;
    long pan = (long)mb * 16 + kb;

    int t = threadIdx.x;
#pragma unroll
    for (int q = 0; q < 4; q++) {
        int ch = t + q * 256;
        int r = ch >> 3;
        int c0 = (ch & 7) * 8;
        const float* sp = src + ((long)mb * 128 + r) * 1024 + kc0 + c0;
        float4 f0 = *(const float4*)sp;
        float4 f1 = *(const float4*)(sp + 4);
        float vals[8] = {f0.x, f0.y, f0.z, f0.w, f1.x, f1.y, f1.z, f1.w};
        union { __half h[8]; uint4 u; } pk;
#pragma unroll
        for (int e = 0; e < 8; e++) pk.h[e] = __float2half_rn(vals[e]);
        uint32_t sw = sw128((uint32_t)(r * 128 + c0 * 2));
        *(uint4*)((char*)(dst + pan * PANEL) + sw) = pk.u;
    }
}

// ---------------- GEMM mainloop, 2-term A (proj): single sync per chunk -----
__device__ __forceinline__ void gemm_mainloop2(
    const char* pA, const char* pW, uint32_t tiles,
    int tid, int rA0, int rB0, int cb, uint32_t xm,
    float acc[2][8][4]) {
    {
        uint32_t sa = tiles;
#pragma unroll
        for (int q = 0; q < 12; q++) {
            int ch = tid + q * 256;
            int reg = ch >> 10;
            int idx = ch & 1023;
            const char* src = (reg == 0) ? (pA + idx * 16)
                            : (reg == 1) ? (pA + 16 * 16384 + idx * 16)
                                         : (pW + idx * 16);
            cp_async16(sa + ch * 16, src);
        }
        CP_COMMIT();
    }

    for (int kb = 0; kb < 16; kb++) {
        CP_WAIT(0);
        __syncthreads();
        if (kb + 1 < 16) {
            uint32_t sa = tiles + (uint32_t)((kb + 1) & 1) * 49152u;
            const char* gAh = pA + (long)(kb + 1) * 16384;
            const char* gAl = pA + (long)(16 + kb + 1) * 16384;
            const char* gW  = pW + (long)(kb + 1) * 16384;
#pragma unroll
            for (int q = 0; q < 12; q++) {
                int ch = tid + q * 256;
                int reg = ch >> 10;
                int idx = ch & 1023;
                const char* src = (reg == 0) ? (gAh + idx * 16)
                                : (reg == 1) ? (gAl + idx * 16)
                                             : (gW + idx * 16);
                cp_async16(sa + ch * 16, src);
            }
            CP_COMMIT();
        }

        uint32_t sA = tiles + (uint32_t)(kb & 1) * 49152u;
        uint32_t sW = sA + 32768u;
#pragma unroll
        for (int ks = 0; ks < 4; ks++) {
            uint32_t colb = (uint32_t)(cb + ks * 32) ^ xm;
            uint32_t bf[4][4];
#pragma unroll
            for (int np = 0; np < 4; np++)
                ldmat_x4(bf[np], sW + (uint32_t)(rB0 + np * 16) * 128u + colb);
#pragma unroll
            for (int half = 0; half < 2; half++) {
                uint32_t aB = sA + (uint32_t)half * 16384u;
                uint32_t af[2][4];
#pragma unroll
                for (int mt = 0; mt < 2; mt++)
                    ldmat_x4(af[mt], aB + (uint32_t)(rA0 + mt * 16) * 128u + colb);
#pragma unroll
                for (int mt = 0; mt < 2; mt++) {
#pragma unroll
                    for (int nt = 0; nt < 8; nt++) {
                        int np = nt >> 1;
                        int sel = nt & 1;
                        mma16816(acc[mt][nt], af[mt], bf[np][sel], bf[np][sel + 2]);
                    }
                }
            }
        }
    }
}

// ---------------- merged projection GEMM -> attention panels ----------------
// grid (48, 32): x<24 ctx qkv, x<40 tgt kv, else tgt q.
__global__ __launch_bounds__(256, 2) void gemm_proj(
    const float* __restrict__ ctx_in_b, const float* __restrict__ tgt_in_b) {
    extern __shared__ char dsm[];
    uint32_t base = smem_u32(dsm);
    uint32_t tiles = (base + 1023u) & ~1023u;

    int tid = threadIdx.x;
    int wid = tid >> 5;
    int lid = tid & 31;
    int wm = wid & 3;
    int wn = wid >> 2;

    int nx = blockIdx.x;
    const __half* Apan;
    const __half* Wpan;
    const float* bias;
    __half* apDst;
    float qscale;
    int nloc;
    if (nx < 24) {
        Apan = g_a2; Wpan = g_wc; bias = ctx_in_b;
        apDst = g_ap; qscale = 0.125f; nloc = nx;
    } else if (nx < 40) {
        Apan = g_a2; Wpan = g_wt + 8ll * 16 * PANEL; bias = tgt_in_b + 1024;
        apDst = g_ap + 8ll * ATT_T; qscale = 1.0f; nloc = nx - 24;
    } else {
        Apan = g_a2 + 8ll * 32 * PANEL; Wpan = g_wt; bias = tgt_in_b;
        apDst = g_ap + 6ll * ATT_T; qscale = 0.125f; nloc = nx - 40;
    }

    int by = blockIdx.y;
    int b = by >> 3;
    int l = by & 7;
    const char* pA = (const char*)(Apan + ((long)(b * 16 + l) * 32) * PANEL);
    const char* pW = (const char*)(Wpan + ((long)nloc * 16) * PANEL);

    float acc[2][8][4];
#pragma unroll
    for (int mt = 0; mt < 2; mt++)
#pragma unroll
        for (int nt = 0; nt < 8; nt++)
#pragma unroll
            for (int e = 0; e < 4; e++) acc[mt][nt][e] = 0.0f;

    int rA0 = wm * 32 + (lid & 15);
    int rB0 = wn * 64 + (lid & 15);
    int cb  = (lid >> 4) * 16;
    uint32_t xm = (uint32_t)((lid & 7) << 4);

    gemm_mainloop2(pA, pW, tiles, tid, rA0, rB0, cb, xm, acc);

    int n0 = nloc * 128;
#pragma unroll
    for (int nt = 0; nt < 8; nt++) {
        int cc = wn * 64 + nt * 8 + (lid & 3) * 2;
        int ng = n0 + cc;
        int g = ng >> 10;
        int head = (ng >> 6) & 15;
        float sc = (g == 0) ? qscale : 1.0f;
        float bx = bias[ng];
        float by2 = bias[ng + 1];
        __half* hiB = apDst + (long)(2 * g) * ATT_T;
        __half* loB = apDst + (long)(2 * g + 1) * ATT_T;
        bool writeLo = (g != 2);   // V-lo panels are unused (PV 1-term)
#pragma unroll
        for (int mt = 0; mt < 2; mt++) {
            int r0 = wm * 32 + mt * 16 + (lid >> 2);
#pragma unroll
            for (int half = 0; half < 2; half++) {
                int tr = l * 128 + r0 + half * 8;
                int kt = tr >> 6;
                int row = tr & 63;
                float vx = (acc[mt][nt][half * 2 + 0] + bx) * sc;
                float vy = (acc[mt][nt][half * 2 + 1] + by2) * sc;
                uint32_t uhi, ulo;
                split2h(vx, vy, uhi, ulo);
                long pan = (((long)b * PH + head) * 16 + kt) * APAN;
                uint32_t sw = sw128((uint32_t)(row * 128 + (nt * 8 + (lid & 3) * 2) * 2));
                *(uint32_t*)((char*)(hiB + pan) + sw) = uhi;
                if (writeLo)
                    *(uint32_t*)((char*)(loB + pan) + sw) = ulo;
            }
        }
    }
}

// ---------------- output projection: 64x128 tiles, 3 CTAs/SM ----------------
// grid (8, 128): y<64 ctx (b=y>>4, sub=y&15), else tgt.
// 8 warps: wm = wid&1 (32 rows), wn = wid>>1 (32 cols). Stage [A 8K|W 16K].
__global__ __launch_bounds__(256, 3) void gemm_out(
    const float* __restrict__ ctx_out_b, const float* __restrict__ tgt_out_b,
    float* __restrict__ C) {
    extern __shared__ char dsm[];
    uint32_t base = smem_u32(dsm);
    uint32_t tiles = (base + 1023u) & ~1023u;

    int tid = threadIdx.x;
    int wid = tid >> 5;
    int lid = tid & 31;
    int wm = wid & 1;
    int wn = wid >> 1;

    int y = blockIdx.y;
    const __half* Apan;
    const __half* Wpan;
    const float* bias;
    int slotOff;
    if (y < 64) {
        Apan = g_oc2; Wpan = g_wco; bias = ctx_out_b; slotOff = 0;
    } else {
        Apan = g_ot2; Wpan = g_wto; bias = tgt_out_b; slotOff = PNC;
        y -= 64;
    }
    int b = y >> 4;
    int sub = y & 15;
    const char* pA = (const char*)(Apan + ((long)(b * 8 + (sub >> 1)) * 16) * PANEL)
                   + (sub & 1) * 8192;
    const char* pW = (const char*)(Wpan + ((long)blockIdx.x * 16) * PANEL);

    float acc[2][4][4];
#pragma unroll
    for (int mt = 0; mt < 2; mt++)
#pragma unroll
        for (int nt = 0; nt < 4; nt++)
#pragma unroll
            for (int e = 0; e < 4; e++) acc[mt][nt][e] = 0.0f;

    int rA0 = wm * 32 + (lid & 15);
    int rB0 = wn * 32 + (lid & 15);
    int cb  = (lid >> 4) * 16;
    uint32_t xm = (uint32_t)((lid & 7) << 4);

    // prologue
    {
        uint32_t sa = tiles;
#pragma unroll
        for (int q = 0; q < 6; q++) {
            int ch = tid + q * 256;
            const char* src = (ch < 512) ? (pA + ch * 16) : (pW + (ch - 512) * 16);
            cp_async16(sa + ch * 16, src);
        }
        CP_COMMIT();
    }

    for (int kb = 0; kb < 16; kb++) {
        CP_WAIT(0);
        __syncthreads();
        if (kb + 1 < 16) {
            uint32_t sa = tiles + (uint32_t)((kb + 1) & 1) * 24576u;
            const char* gA = pA + (long)(kb + 1) * 16384;
            const char* gW = pW + (long)(kb + 1) * 16384;
#pragma unroll
            for (int q = 0; q < 6; q++) {
                int ch = tid + q * 256;
                const char* src = (ch < 512) ? (gA + ch * 16) : (gW + (ch - 512) * 16);
                cp_async16(sa + ch * 16, src);
            }
            CP_COMMIT();
        }

        uint32_t sA = tiles + (uint32_t)(kb & 1) * 24576u;
        uint32_t sW = sA + 8192u;
#pragma unroll
        for (int ks = 0; ks < 4; ks++) {
            uint32_t colb = (uint32_t)(cb + ks * 32) ^ xm;
            uint32_t bf[2][4];
#pragma unroll
            for (int np = 0; np < 2; np++)
                ldmat_x4(bf[np], sW + (uint32_t)(rB0 + np * 16) * 128u + colb);
            uint32_t af[2][4];
#pragma unroll
            for (int mt = 0; mt < 2; mt++)
                ldmat_x4(af[mt], sA + (uint32_t)(rA0 + mt * 16) * 128u + colb);
#pragma unroll
            for (int mt = 0; mt < 2; mt++) {
#pragma unroll
                for (int nt = 0; nt < 4; nt++) {
                    int np = nt >> 1;
                    int sel = nt & 1;
                    mma16816(acc[mt][nt], af[mt], bf[np][sel], bf[np][sel + 2]);
                }
            }
        }
    }

    int n0 = blockIdx.x * 128;
#pragma unroll
    for (int nt = 0; nt < 4; nt++) {
        int cc = wn * 32 + nt * 8 + (lid & 3) * 2;
        float2 bv;
        bv.x = bias[n0 + cc];
        bv.y = bias[n0 + cc + 1];
#pragma unroll
        for (int mt = 0; mt < 2; mt++) {
            int r0 = wm * 32 + mt * 16 + (lid >> 2);
            float2 v0, v1;
            v0.x = acc[mt][nt][0] + bv.x;
            v0.y = acc[mt][nt][1] + bv.y;
            v1.x = acc[mt][nt][2] + bv.x;
            v1.y = acc[mt][nt][3] + bv.y;
            int tok0 = g_perm[b * PK + sub * 64 + r0 + slotOff];
            int tok1 = g_perm[b * PK + sub * 64 + r0 + 8 + slotOff];
            *(float2*)(C + ((long)b * PK + tok0) * PD + n0 + cc) = v0;
            *(float2*)(C + ((long)b * PK + tok1) * PD + n0 + cc) = v1;
        }
    }
}

// ---------------- merged fp16 HMMA flash attention --------------------------
// grid (8, 16, 8): z<4 ctx (b=z), else tgt (b=z-4). QK 3-term, PV 1-term.
__global__ __launch_bounds__(256, 2) void attn_mma() {
    extern __shared__ char dsm[];
    uint32_t base = smem_u32(dsm);
    uint32_t sQ = (base + 1023u) & ~1023u;     // Qh 16KB | Ql 16KB
    uint32_t sT = sQ + 32768u;                 // 2 stages x [Kh|Kl|Vh] 8KB each

    int tid = threadIdx.x, wid = tid >> 5, lid = tid & 31;
    int qt = blockIdx.x, h = blockIdx.y, z = blockIdx.z;
    int b;
    const __half* baseAp;
    __half* Opan;
    if (z < 4) { b = z;     baseAp = g_ap;                 Opan = g_oc2; }
    else       { b = z - 4; baseAp = g_ap + 6ll * ATT_T;   Opan = g_ot2; }

    long pb = ((long)b * PH + h) * 16;
    const char* pQh = (const char*)(baseAp + 0ll * ATT_T + (pb + qt * 2) * APAN);
    const char* pQl = (const char*)(baseAp + 1ll * ATT_T + (pb + qt * 2) * APAN);
    const char* pKh = (const char*)(baseAp + 2ll * ATT_T + pb * APAN);
    const char* pKl = (const char*)(baseAp + 3ll * ATT_T + pb * APAN);
    const char* pVh = (const char*)(baseAp + 4ll * ATT_T + pb * APAN);

#pragma unroll
    for (int q = 0; q < 8; q++) {
        int ch = tid + q * 256;
        int idx = ch & 1023;
        if (q < 4) cp_async16(sQ + idx * 16, pQh + idx * 16);
        else       cp_async16(sQ + 16384 + idx * 16, pQl + idx * 16);
    }
#pragma unroll
    for (int q = 0; q < 6; q++) {
        int ch = tid + q * 256;
        int idx = ch & 511;
        const char* s = (q < 2) ? pKh : (q < 4) ? pKl : pVh;
        cp_async16(sT + ch * 16, s + idx * 16);
    }
    CP_COMMIT();
    CP_WAIT(0);
    __syncthreads();

    int cb = (lid >> 4) * 16;
    uint32_t xm = (uint32_t)((lid & 7) << 4);

    uint32_t qra = sQ + (uint32_t)(wid >> 2) * 8192u
                 + (uint32_t)(((wid & 3) * 16 + (lid & 15)) * 128);
    uint32_t qhf[4][4], qlf[4][4];
#pragma unroll
    for (int ks = 0; ks < 4; ks++) {
        uint32_t col = (uint32_t)(ks * 32 + cb) ^ xm;
        ldmat_x4(qhf[ks], qra + col);
        ldmat_x4(qlf[ks], qra + 16384u + col);
    }

    float m0 = -1e30f, m1 = -1e30f, l0 = 0.0f, l1 = 0.0f;
    float oa[8][4];
#pragma unroll
    for (int nt = 0; nt < 8; nt++)
#pragma unroll
        for (int e = 0; e < 4; e++) oa[nt][e] = 0.0f;

    for (int kt = 0; kt < 16; kt++) {
        uint32_t st = sT + (uint32_t)(kt & 1) * 24576u;
        if (kt + 1 < 16) {
            uint32_t sn = sT + (uint32_t)((kt + 1) & 1) * 24576u;
            long off = (long)(kt + 1) * 8192;
#pragma unroll
            for (int q = 0; q < 6; q++) {
                int ch = tid + q * 256;
                int idx = ch & 511;
                const char* s = (q < 2) ? pKh : (q < 4) ? pKl : pVh;
                cp_async16(sn + ch * 16, s + off + idx * 16);
            }
            CP_COMMIT();
        }

        float sc[8][4];
#pragma unroll
        for (int nt = 0; nt < 8; nt++)
#pragma unroll
            for (int e = 0; e < 4; e++) sc[nt][e] = 0.0f;

#pragma unroll
        for (int ks = 0; ks < 4; ks++) {
            uint32_t col = (uint32_t)(ks * 32 + cb) ^ xm;
            uint32_t bh_[4][4], bl_[4][4];
#pragma unroll
            for (int np = 0; np < 4; np++) {
                uint32_t ra = (uint32_t)((np * 16 + (lid & 15)) * 128);
                ldmat_x4(bh_[np], st + ra + col);
                ldmat_x4(bl_[np], st + 8192u + ra + col);
            }
#pragma unroll
            for (int nt = 0; nt < 8; nt++) {
                int np = nt >> 1, sel = nt & 1;
                mma16816(sc[nt], qhf[ks], bh_[np][sel], bh_[np][sel + 2]);
                mma16816(sc[nt], qlf[ks], bh_[np][sel], bh_[np][sel + 2]);
                mma16816(sc[nt], qhf[ks], bl_[np][sel], bl_[np][sel + 2]);
            }
        }

        float mt0 = -1e30f, mt1 = -1e30f;
#pragma unroll
        for (int nt = 0; nt < 8; nt++) {
            mt0 = fmaxf(mt0, fmaxf(sc[nt][0], sc[nt][1]));
            mt1 = fmaxf(mt1, fmaxf(sc[nt][2], sc[nt][3]));
        }
        mt0 = fmaxf(mt0, __shfl_xor_sync(0xffffffffu, mt0, 1));
        mt0 = fmaxf(mt0, __shfl_xor_sync(0xffffffffu, mt0, 2));
        mt1 = fmaxf(mt1, __shfl_xor_sync(0xffffffffu, mt1, 1));
        mt1 = fmaxf(mt1, __shfl_xor_sync(0xffffffffu, mt1, 2));

        float mn0 = fmaxf(m0, mt0), mn1 = fmaxf(m1, mt1);
        float a0 = __expf(m0 - mn0), a1 = __expf(m1 - mn1);

        uint32_t php[8][2];
        float ps0 = 0.0f, ps1 = 0.0f;
#pragma unroll
        for (int nt = 0; nt < 8; nt++) {
            float p00 = __expf(sc[nt][0] - mn0);
            float p01 = __expf(sc[nt][1] - mn0);
            float p10 = __expf(sc[nt][2] - mn1);
            float p11 = __expf(sc[nt][3] - mn1);
            ps0 += p00 + p01;
            ps1 += p10 + p11;
            php[nt][0] = packh2(p00, p01);
            php[nt][1] = packh2(p10, p11);
        }
        ps0 += __shfl_xor_sync(0xffffffffu, ps0, 1);
        ps0 += __shfl_xor_sync(0xffffffffu, ps0, 2);
        ps1 += __shfl_xor_sync(0xffffffffu, ps1, 1);
        ps1 += __shfl_xor_sync(0xffffffffu, ps1, 2);

        l0 = l0 * a0 + ps0;
        l1 = l1 * a1 + ps1;
        m0 = mn0;
        m1 = mn1;
#pragma unroll
        for (int nt = 0; nt < 8; nt++) {
            oa[nt][0] *= a0; oa[nt][1] *= a0;
            oa[nt][2] *= a1; oa[nt][3] *= a1;
        }

#pragma unroll
        for (int ks = 0; ks < 4; ks++) {
            uint32_t ah[4] = {php[2 * ks][0], php[2 * ks][1],
                              php[2 * ks + 1][0], php[2 * ks + 1][1]};
            uint32_t vh_[4][4];
            uint32_t ra = (uint32_t)((ks * 16 + (lid & 15)) * 128);
#pragma unroll
            for (int np = 0; np < 4; np++) {
                uint32_t col = (uint32_t)(np * 32 + cb) ^ xm;
                ldmat_x4_trans(vh_[np], st + 16384u + ra + col);
            }
#pragma unroll
            for (int nt = 0; nt < 8; nt++) {
                int np = nt >> 1, s2 = (nt & 1) * 2;
                mma16816(oa[nt], ah, vh_[np][s2], vh_[np][s2 + 1]);
            }
        }

        if (kt + 1 < 16) CP_WAIT(0);
        __syncthreads();
    }

    // epilogue: hi-only A-panels [mb = b*8+qt][16 chunks]; chunk h
    float i0 = 1.0f / l0, i1 = 1.0f / l1;
    int rl = wid * 16 + (lid >> 2);
    long panB = ((long)b * 8 + qt) * 16;
    __half* c_hi = Opan + (panB + h) * (long)PANEL;
#pragma unroll
    for (int nt = 0; nt < 8; nt++) {
        int col = nt * 8 + (lid & 3) * 2;
        uint32_t sw0 = sw128((uint32_t)(rl * 128 + col * 2));
        uint32_t sw1 = sw128((uint32_t)((rl + 8) * 128 + col * 2));
        *(uint32_t*)((char*)c_hi + sw0) = packh2(oa[nt][0] * i0, oa[nt][1] * i0);
        *(uint32_t*)((char*)c_hi + sw1) = packh2(oa[nt][2] * i1, oa[nt][3] * i1);
    }
}

// ---------------- launch ----------------
extern "C" void kernel_launch(void* const* d_in, const int* in_sizes, int n_in,
                              void* d_out, int out_size) {
    const float* x         = (const float*)d_in[0];
    const float* coords    = (const float*)d_in[1];
    const void*  is_ctx    = d_in[2];
    const float* rope      = (const float*)d_in[3];
    const float* ctx_in_w  = (const float*)d_in[4];
    const float* ctx_in_b  = (const float*)d_in[5];
    const float* ctx_out_w = (const float*)d_in[6];
    const float* ctx_out_b = (const float*)d_in[7];
    const float* tgt_in_w  = (const float*)d_in[8];
    const float* tgt_in_b  = (const float*)d_in[9];
    const float* tgt_out_w = (const float*)d_in[10];
    const float* tgt_out_b = (const float*)d_in[11];
    float* out = (float*)d_out;

    const int GSM  = 1024 + 2 * 49152;           // 99328 (proj)
    const int GSM1 = 1024 + 2 * 24576;           // 50176 (out, 64x128)
    const int ASM  = 1024 + 32768 + 2 * 24576;   // 82944
    cudaFuncSetAttribute(gemm_proj, cudaFuncAttributeMaxDynamicSharedMemorySize, GSM);
    cudaFuncSetAttribute(gemm_out,  cudaFuncAttributeMaxDynamicSharedMemorySize, GSM1);
    cudaFuncSetAttribute(attn_mma,  cudaFuncAttributeMaxDynamicSharedMemorySize, ASM);

    build_perm<<<PB, 32>>>(is_ctx);
    rope_gather<<<PB * PK, 512>>>(x, coords, rope);
    convert_w_all<<<64 * 16, 256>>>(ctx_in_w, tgt_in_w, ctx_out_w, tgt_out_w);
    gemm_proj<<<dim3(48, 32), 256, GSM>>>(ctx_in_b, tgt_in_b);
    attn_mma<<<dim3(8, PH, 2 * PB), 256, ASM>>>();
    gemm_out<<<dim3(8, 128), 256, GSM1>>>(ctx_out_b, tgt_out_b, out);
}